// round 17
// baseline (speedup 1.0000x reference)
#include <cuda_runtime.h>
#include <math.h>

#define NCH   256
#define OUTSZ 7
#define GRIDY 32                 // channel splits
#define CPB   (NCH / GRIDY)      // 8 channels per block
#define NWARP 2                  // 64-thread blocks
#define CPW   (CPB / NWARP)      // 4 channels per warp -> one fused body
#define MAXROI 1024

// per-ROI precomputed tables (written by tab_kernel, read by main kernel)
__device__ __align__(16) float2 g_xw[MAXROI * 32];   // (xc as int bits, wx)
__device__ __align__(16) int    g_ry[MAXROI * 32];   // y row offsets (28 used)
__device__ __align__(16) float  g_wy[MAXROI * 32];   // y weights     (28 used)
__device__ int g_lvl[MAXROI];

__global__ __launch_bounds__(64, 24)
void tab_kernel(const float* __restrict__ boxes, int nroi)
{
    const int roi = blockIdx.x;
    const int tid = threadIdx.x;

    const float bx1 = boxes[roi * 4 + 0];
    const float by1 = boxes[roi * 4 + 1];
    const float bx2 = boxes[roi * 4 + 2];
    const float by2 = boxes[roi * 4 + 3];

    float area = (bx2 - bx1) * (by2 - by1);
    float s    = sqrtf(fmaxf(area, 0.0f));
    float lvlf = floorf(4.0f + log2f(s / 224.0f) + 1e-6f);
    lvlf = fminf(fmaxf(lvlf, 2.0f), 5.0f);
    const int lvl = (int)lvlf - 2;                 // 0..3

    const int   Hs[4]  = {200, 100, 50, 25};
    const float scs[4] = {0.25f, 0.125f, 0.0625f, 0.03125f};
    const int   H = Hs[lvl];
    const int   W = H;
    const float scale = scs[lvl];

    if (tid < 32) {
        // ---- x tap tables (taps 28..31 zero-weight, index 0) ----
        const int g = tid;
        int   xc = 0;
        float w  = 0.0f;
        if (g < 28) {
            const int gx = g >> 1;
            const int xt = g & 1;
            const float c1 = bx1 * scale;
            const float c2 = bx2 * scale;
            const float bin = fmaxf(c2 - c1, 1.0f) / (float)OUTSZ;
            const float coord = c1 + (float)(gx >> 1) * bin
                                   + ((float)(gx & 1) + 0.5f) * bin / 2.0f;
            const bool valid = (coord >= -1.0f) && (coord <= (float)W);
            const float cc = fminf(fmaxf(coord, 0.0f), (float)(W - 1));
            const int i0 = (int)floorf(cc);
            const int i1 = min(i0 + 1, W - 1);
            const float l = cc - (float)i0;
            const float h = 1.0f - l;
            xc = xt ? i1 : i0;
            w  = valid ? (xt ? l : h) * 0.25f : 0.0f;   // fold the 1/4 bin average
        }
        g_xw[roi * 32 + g] = make_float2(__int_as_float(xc), w);
    } else {
        // ---- y tap tables (threads 32..63) ----
        const int g = tid - 32;
        if (g < 28) {
            const int gy = g >> 1;
            const int yt = g & 1;
            const float c1 = by1 * scale;
            const float c2 = by2 * scale;
            const float bin = fmaxf(c2 - c1, 1.0f) / (float)OUTSZ;
            const float coord = c1 + (float)(gy >> 1) * bin
                                   + ((float)(gy & 1) + 0.5f) * bin / 2.0f;
            const bool valid = (coord >= -1.0f) && (coord <= (float)H);
            const float cc = fminf(fmaxf(coord, 0.0f), (float)(H - 1));
            const int i0 = (int)floorf(cc);
            const int i1 = min(i0 + 1, H - 1);
            const float l = cc - (float)i0;
            const float h = 1.0f - l;
            g_ry[roi * 32 + g] = (yt ? i1 : i0) * W;
            g_wy[roi * 32 + g] = valid ? (yt ? l : h) : 0.0f;
        } else if (g == 28) {
            g_lvl[roi] = lvl;
        }
    }
}

__global__ __launch_bounds__(64, 24)
void msroi_kernel(const float* __restrict__ f0,
                  const float* __restrict__ f1,
                  const float* __restrict__ f2,
                  const float* __restrict__ f3,
                  float* __restrict__ out,
                  int nroi)
{
    const int roi  = blockIdx.x;
    const int tid  = threadIdx.x;
    const int warp = tid >> 5;
    const int lane = tid & 31;

    // ---- minimal preamble: everything precomputed ----
    const float2 xw = __ldg(&g_xw[roi * 32 + lane]);
    const int    xc = __float_as_int(xw.x);
    const float  wx = xw.y;
    const int   lvl = __ldg(&g_lvl[roi]);

    const int Hs[4] = {200, 100, 50, 25};
    const int H  = Hs[lvl];
    const int HW = H * H;
    const float* fl = (lvl == 0) ? f0 : (lvl == 1) ? f1
                    : (lvl == 2) ? f2 : f3;
    const int b = (roi >= (nroi >> 1)) ? 1 : 0;    // B = 2
    const float* base = fl + (size_t)b * (size_t)NCH * (size_t)HW;

    const bool act  = lane < 28;        // lanes 28..31 fully predicated off
    const bool odd1 = (lane & 1) != 0;
    const bool odd2 = (lane & 2) != 0;

    const int c0 = blockIdx.y * CPB + warp * CPW;
    const float* q = base + (size_t)c0 * HW + xc;

    // after the 3-shuffle transpose-reduce, lane (4g+k) holds channel c0+k,
    // bin bx = g  -> identity channel map, contiguous output runs.
    float* o = out + (size_t)roi * (NCH * OUTSZ * OUTSZ)
                   + (size_t)(c0 + (lane & 3)) * (OUTSZ * OUTSZ) + (lane >> 2);

    const int4*   ry4 = (const int4*)&g_ry[roi * 32];
    const float4* wy4 = (const float4*)&g_wy[roi * 32];

    #pragma unroll
    for (int by = 0; by < OUTSZ; ++by) {
        const int4   r = __ldg(&ry4[by]);   // uniform-address broadcast, L1-hot
        const float4 w = __ldg(&wy4[by]);

        float a = 0.0f, b2 = 0.0f, c = 0.0f, d = 0.0f;
        if (act) {
            const float* q1 = q + HW;
            const float* q2 = q + 2 * HW;
            const float* q3 = q + 3 * HW;
            a  =      w.x * __ldg(q  + r.x);
            b2 =      w.x * __ldg(q1 + r.x);
            c  =      w.x * __ldg(q2 + r.x);
            d  =      w.x * __ldg(q3 + r.x);
            a  = fmaf(w.y,  __ldg(q  + r.y), a);
            b2 = fmaf(w.y,  __ldg(q1 + r.y), b2);
            c  = fmaf(w.y,  __ldg(q2 + r.y), c);
            d  = fmaf(w.y,  __ldg(q3 + r.y), d);
            a  = fmaf(w.z,  __ldg(q  + r.z), a);
            b2 = fmaf(w.z,  __ldg(q1 + r.z), b2);
            c  = fmaf(w.z,  __ldg(q2 + r.z), c);
            d  = fmaf(w.z,  __ldg(q3 + r.z), d);
            a  = fmaf(w.w,  __ldg(q  + r.w), a);
            b2 = fmaf(w.w,  __ldg(q1 + r.w), b2);
            c  = fmaf(w.w,  __ldg(q2 + r.w), c);
            d  = fmaf(w.w,  __ldg(q3 + r.w), d);
            a *= wx;  b2 *= wx;  c *= wx;  d *= wx;
        }

        // --- 3-shuffle 4x4 transpose-reduce ---
        float t1 = odd1 ? a : b2;
        t1 = __shfl_xor_sync(0xffffffffu, t1, 1);
        const float X = (odd1 ? b2 : a) + t1;

        float t2 = odd1 ? c : d;
        t2 = __shfl_xor_sync(0xffffffffu, t2, 1);
        const float Y = (odd1 ? d : c) + t2;

        float t3 = odd2 ? X : Y;
        t3 = __shfl_xor_sync(0xffffffffu, t3, 2);
        const float res = (odd2 ? Y : X) + t3;

        if (act) __stcs(o + by * OUTSZ, res);
    }
}

extern "C" void kernel_launch(void* const* d_in, const int* in_sizes, int n_in,
                              void* d_out, int out_size)
{
    const float* f0 = (const float*)d_in[0];
    const float* f1 = (const float*)d_in[1];
    const float* f2 = (const float*)d_in[2];
    const float* f3 = (const float*)d_in[3];
    const float* bx = (const float*)d_in[4];
    float* out = (float*)d_out;

    const int nroi = in_sizes[4] / 4;              // 512
    tab_kernel<<<nroi, 64>>>(bx, nroi);
    dim3 grid(nroi, GRIDY, 1);                     // 512 x 32
    msroi_kernel<<<grid, 64>>>(f0, f1, f2, f3, out, nroi);
}